// round 8
// baseline (speedup 1.0000x reference)
#include <cuda_runtime.h>

// x: [B=16, T=4096, D=1024] f32, out: [B, D] = sum over T.
// Balanced fused reduction:
//   grid = 444 = 3 * 148 SMs -> exactly 3 resident CTAs per SM, per-SM bytes
//   balanced to +-1 row (kills the 4-vs-3 CTA straggler tail of grid=512).
//   Block i owns contiguous rows [i*65536/444, (i+1)*65536/444) (147-148
//   rows, sequential streaming = proven-fastest DRAM pattern, unroll 8).
//   A range straddles at most one batch boundary -> <=2 segments, each
//   written to static partial slot 2i+seg. Per-batch atomic ticket; the last
//   finisher reduces its batch's ~28 slots with fully-unrolled independent
//   loads (MLP~28, one L2 latency) in fixed ascending order (deterministic)
//   and resets the ticket (graph-replay safe).

#define B_DIM 16
#define T_DIM 4096
#define D_DIM 1024
#define D4 (D_DIM / 4)              // 256 float4 per row
#define TOTAL_ROWS (B_DIM * T_DIM)  // 65536
#define GRID 444
#define MAX_SEGS_PER_BATCH 29       // ceil(4096/147)+1 safety

__device__ float g_partial[2 * GRID * D_DIM];   // slot = 2i+seg
__device__ int g_count[B_DIM];                  // zero-init; reset by reducer

__device__ __forceinline__ int row_start(int i) {
    return (int)((long long)i * TOTAL_ROWS / GRID);
}
__device__ __forceinline__ int block_of_row(int r) {
    return (int)(((long long)(r + 1) * GRID - 1) / TOTAL_ROWS);
}

__global__ __launch_bounds__(256, 8)
void sum_balanced(const float* __restrict__ x, float* __restrict__ out) {
    const int i   = blockIdx.x;       // 0..443
    const int tid = threadIdx.x;      // 0..255 -> one float4 column

    const int r0 = row_start(i);
    const int r1 = row_start(i + 1);
    const int b0 = r0 / T_DIM;
    const int bsplit = (b0 + 1) * T_DIM;

    const float4* __restrict__ x4 = reinterpret_cast<const float4*>(x);
    float4* __restrict__ p4 = reinterpret_cast<float4*>(g_partial);
    __shared__ int s_ticket;

    #pragma unroll
    for (int seg = 0; seg < 2; ++seg) {
        const int rs = seg ? bsplit : r0;
        const int re = seg ? r1 : (r1 < bsplit ? r1 : bsplit);
        if (rs >= re) continue;
        const int b = b0 + seg;

        // Sequential stream over contiguous rows, unroll 8 (proven config).
        const float4* __restrict__ xp = x4 + (size_t)rs * D4 + tid;
        const int nrows = re - rs;
        float4 acc = make_float4(0.f, 0.f, 0.f, 0.f);
        #pragma unroll 8
        for (int r = 0; r < nrows; ++r) {
            float4 v = __ldg(xp + (size_t)r * D4);
            acc.x += v.x; acc.y += v.y; acc.z += v.z; acc.w += v.w;
        }
        p4[(size_t)(2 * i + seg) * D4 + tid] = acc;

        __threadfence();
        __syncthreads();                 // all stores issued before ticket
        if (tid == 0) s_ticket = atomicAdd(&g_count[b], 1);
        __syncthreads();
        const int my_ticket = s_ticket;

        const int iF = block_of_row(b * T_DIM);
        const int iL = block_of_row(b * T_DIM + T_DIM - 1);
        const int nseg = iL - iF + 1;

        if (my_ticket == nseg - 1) {
            // Last finisher for batch b: independent (unrolled) slot loads.
            float4 rsum = make_float4(0.f, 0.f, 0.f, 0.f);
            #pragma unroll
            for (int k = 0; k < MAX_SEGS_PER_BATCH; ++k) {
                const int j = iF + k;
                if (j > iL) break;
                const int slot = 2 * j + ((row_start(j) / T_DIM) == b ? 0 : 1);
                float4 v = p4[(size_t)slot * D4 + tid];
                rsum.x += v.x; rsum.y += v.y; rsum.z += v.z; rsum.w += v.w;
            }
            reinterpret_cast<float4*>(out)[(size_t)b * D4 + tid] = rsum;
            if (tid == 0) g_count[b] = 0;   // graph-replay safe
        }
    }
}

extern "C" void kernel_launch(void* const* d_in, const int* in_sizes, int n_in,
                              void* d_out, int out_size) {
    const float* x = (const float*)d_in[0];
    float* out = (float*)d_out;
    sum_balanced<<<GRID, 256>>>(x, out);
}

// round 13
// speedup vs baseline: 1.3580x; 1.3580x over previous
#include <cuda_runtime.h>

// x: [B=16, T=4096, D=1024] f32, out: [B, D] = sum over T.
// Balanced fused reduction, static loops, CORRECT ticket protocol:
//   Per batch: 37 blocks = 26 x 111 + 11 x 110 rows = 4096 (no straddle ->
//   compile-time trip counts, unroll 8, __ldcs stream).
//   Grid = 16*37 = 592 = 4*148 -> exactly 4 CTAs per SM, bytes balanced
//   to +-1 row.
//   Ticket protocol (R9/R10 bug): __threadfence() alone only orders each
//   thread's OWN stores; tid0's atomicAdd needs a __syncthreads() AFTER the
//   fence so all 256 threads' partial stores are globally visible before
//   the ticket is taken. Reducer takes an acquire fence before reading.

#define B_DIM 16
#define T_DIM 4096
#define D_DIM 1024
#define D4 (D_DIM / 4)          // 256 float4 per row
#define BPB 37                  // blocks per batch
#define HEAVY 26                // first 26 blocks: 111 rows; rest: 110
#define GRID (B_DIM * BPB)      // 592 = 4 * 148

__device__ float g_partial[GRID * D_DIM];   // slot = blockIdx.x
__device__ int g_count[B_DIM];              // zero-init; reset by reducer

template <int NROWS>
__device__ __forceinline__ float4 stream_rows(const float4* __restrict__ xp) {
    float4 acc = make_float4(0.f, 0.f, 0.f, 0.f);
    #pragma unroll 8
    for (int r = 0; r < NROWS; ++r) {
        float4 v = __ldcs(xp + (size_t)r * D4);
        acc.x += v.x; acc.y += v.y; acc.z += v.z; acc.w += v.w;
    }
    return acc;
}

__global__ __launch_bounds__(256, 8)
void sum_fused(const float* __restrict__ x, float* __restrict__ out) {
    const int j   = blockIdx.x;        // 0..591
    const int tid = threadIdx.x;       // 0..255 -> one float4 column
    const int b   = j / BPB;           // batch
    const int w   = j - b * BPB;       // 0..36 within batch

    const int rstart = (w < HEAVY) ? w * 111 : HEAVY * 111 + (w - HEAVY) * 110;

    const float4* __restrict__ xp = reinterpret_cast<const float4*>(x)
        + ((size_t)b * T_DIM + rstart) * D4 + tid;

    float4 acc = (w < HEAVY) ? stream_rows<111>(xp) : stream_rows<110>(xp);

    reinterpret_cast<float4*>(g_partial)[(size_t)j * D4 + tid] = acc;

    // Release side: every thread fences its own store, THEN the block
    // rendezvous, THEN tid0 publishes via the atomic ticket.
    __threadfence();
    __syncthreads();
    __shared__ int s_is_last;
    if (tid == 0) {
        int ticket = atomicAdd(&g_count[b], 1);
        s_is_last = (ticket == BPB - 1);
    }
    __syncthreads();

    if (s_is_last) {
        __threadfence();   // acquire side: order slot reads after ticket win
        const float4* base =
            reinterpret_cast<const float4*>(g_partial) + (size_t)b * BPB * D4;
        float4 rsum = make_float4(0.f, 0.f, 0.f, 0.f);
        #pragma unroll
        for (int k = 0; k < BPB; ++k) {
            float4 v = base[(size_t)k * D4 + tid];   // coherent ld.global
            rsum.x += v.x; rsum.y += v.y; rsum.z += v.z; rsum.w += v.w;
        }
        reinterpret_cast<float4*>(out)[(size_t)b * D4 + tid] = rsum;
        __syncthreads();                 // all reads done before reset
        if (tid == 0) g_count[b] = 0;    // graph-replay safe
    }
}

extern "C" void kernel_launch(void* const* d_in, const int* in_sizes, int n_in,
                              void* d_out, int out_size) {
    const float* x = (const float*)d_in[0];
    float* out = (float*)d_out;
    sum_fused<<<GRID, 256>>>(x, out);
}

// round 14
// speedup vs baseline: 1.4141x; 1.0413x over previous
#include <cuda_runtime.h>

// x: [B=16, T=4096, D=1024] f32, out: [B, D] = sum over T.
// R13 (balanced grid, validated ticket protocol) + ONE change: register
// budget. __launch_bounds__(256,4) -> 64 regs (was (256,8) -> 32 regs,
// which capped in-flight LDG.128s at ~4/thread and pinned DRAM at ~71%).
// Dual accumulators halve the FADD chain; unroll 16 lets ptxas front-batch
// ~8 outstanding loads per thread.

#define B_DIM 16
#define T_DIM 4096
#define D_DIM 1024
#define D4 (D_DIM / 4)          // 256 float4 per row
#define BPB 37                  // blocks per batch
#define HEAVY 26                // first 26 blocks: 111 rows; rest: 110
#define GRID (B_DIM * BPB)      // 592 = 4 * 148

__device__ float g_partial[GRID * D_DIM];   // slot = blockIdx.x
__device__ int g_count[B_DIM];              // zero-init; reset by reducer

template <int NROWS>
__device__ __forceinline__ float4 stream_rows(const float4* __restrict__ xp) {
    float4 a0 = make_float4(0.f, 0.f, 0.f, 0.f);
    float4 a1 = make_float4(0.f, 0.f, 0.f, 0.f);
    int r = 0;
    #pragma unroll 16
    for (; r + 1 < NROWS; r += 2) {
        float4 v0 = __ldcs(xp + (size_t)r * D4);
        float4 v1 = __ldcs(xp + (size_t)(r + 1) * D4);
        a0.x += v0.x; a0.y += v0.y; a0.z += v0.z; a0.w += v0.w;
        a1.x += v1.x; a1.y += v1.y; a1.z += v1.z; a1.w += v1.w;
    }
    if (r < NROWS) {
        float4 v = __ldcs(xp + (size_t)r * D4);
        a0.x += v.x; a0.y += v.y; a0.z += v.z; a0.w += v.w;
    }
    a0.x += a1.x; a0.y += a1.y; a0.z += a1.z; a0.w += a1.w;
    return a0;
}

__global__ __launch_bounds__(256, 4)
void sum_fused(const float* __restrict__ x, float* __restrict__ out) {
    const int j   = blockIdx.x;        // 0..591
    const int tid = threadIdx.x;       // 0..255 -> one float4 column
    const int b   = j / BPB;           // batch
    const int w   = j - b * BPB;       // 0..36 within batch

    const int rstart = (w < HEAVY) ? w * 111 : HEAVY * 111 + (w - HEAVY) * 110;

    const float4* __restrict__ xp = reinterpret_cast<const float4*>(x)
        + ((size_t)b * T_DIM + rstart) * D4 + tid;

    float4 acc = (w < HEAVY) ? stream_rows<111>(xp) : stream_rows<110>(xp);

    reinterpret_cast<float4*>(g_partial)[(size_t)j * D4 + tid] = acc;

    // Release: own-store fence, block rendezvous, then tid0 takes ticket.
    __threadfence();
    __syncthreads();
    __shared__ int s_is_last;
    if (tid == 0) {
        int ticket = atomicAdd(&g_count[b], 1);
        s_is_last = (ticket == BPB - 1);
    }
    __syncthreads();

    if (s_is_last) {
        __threadfence();   // acquire: order slot reads after ticket win
        const float4* base =
            reinterpret_cast<const float4*>(g_partial) + (size_t)b * BPB * D4;
        float4 rsum = make_float4(0.f, 0.f, 0.f, 0.f);
        #pragma unroll
        for (int k = 0; k < BPB; ++k) {
            float4 v = base[(size_t)k * D4 + tid];   // coherent ld.global
            rsum.x += v.x; rsum.y += v.y; rsum.z += v.z; rsum.w += v.w;
        }
        reinterpret_cast<float4*>(out)[(size_t)b * D4 + tid] = rsum;
        __syncthreads();                 // all reads done before reset
        if (tid == 0) g_count[b] = 0;    // graph-replay safe
    }
}

extern "C" void kernel_launch(void* const* d_in, const int* in_sizes, int n_in,
                              void* d_out, int out_size) {
    const float* x = (const float*)d_in[0];
    float* out = (float*)d_out;
    sum_fused<<<GRID, 256>>>(x, out);
}